// round 7
// baseline (speedup 1.0000x reference)
#include <cuda_runtime.h>
#include <math.h>
#include <stdint.h>

// Problem constants: B=16, SEG=512, MEM=512, TOTAL=1024, MD=128, H=8, D=128

// ---------------- scratch ----------------
__device__ float g_h   [16 * 1024 * 128];          // concat(mem,x)      8 MB
__device__ float g_qf  [16 * 512 * 1024];          // x@Wq              32 MB
__device__ float g_kvf [16 * 1024 * 2048];         // h@Wkv            128 MB
__device__ float g_rf  [1024 * 1024];              // R@Wr               4 MB
__device__ float g_att [16 * 512 * 1024];          // attention out     32 MB
__device__ float g_y   [16 * 512 * 128];           // pre-LN y           4 MB

// ---------------- tf32 helpers ----------------
__device__ __forceinline__ uint32_t f2tf(float f) {
    uint32_t u; asm("cvt.rna.tf32.f32 %0, %1;" : "=r"(u) : "f"(f)); return u;
}
__device__ __forceinline__ uint4 cvt4(float4 v) {
    return make_uint4(f2tf(v.x), f2tf(v.y), f2tf(v.z), f2tf(v.w));
}
__device__ __forceinline__ void mma8(float4& c, const uint32_t a[4], uint32_t b0, uint32_t b1) {
    asm volatile("mma.sync.aligned.m16n8k8.row.col.f32.tf32.tf32.f32 "
        "{%0,%1,%2,%3}, {%4,%5,%6,%7}, {%8,%9}, {%0,%1,%2,%3};"
        : "+f"(c.x), "+f"(c.y), "+f"(c.z), "+f"(c.w)
        : "r"(a[0]), "r"(a[1]), "r"(a[2]), "r"(a[3]), "r"(b0), "r"(b1));
}

// ---------------- concat(mem, x) -> g_h ----------------
__global__ __launch_bounds__(256) void concat_kernel(
    const float* __restrict__ x, const float* __restrict__ mem, float* __restrict__ hout)
{
    long idx = (long)blockIdx.x * blockDim.x + threadIdx.x;
    long e = idx * 4;
    int b   = (int)(e >> 17);
    int rem = (int)(e & 131071);
    float4 v;
    if (rem < 65536)  v = *(const float4*)(mem + (long)b * 65536 + rem);
    else              v = *(const float4*)(x   + (long)b * 65536 + rem - 65536);
    *(float4*)(hout + e) = v;
}

// ---------------- tf32 NN GEMM (block 128x128, BK=32, 256 thr) ----------------
__global__ __launch_bounds__(256) void gemm_tf32(
    const float* __restrict__ Ab, const float* __restrict__ Bb, float* __restrict__ Cb,
    int M, int N, int K, long sA, long sB, long sC, const float* __restrict__ resid)
{
    const float* A = Ab + (long)blockIdx.z * sA;
    const float* B = Bb + (long)blockIdx.z * sB;
    float*       C = Cb + (long)blockIdx.z * sC;

    __shared__ __align__(16) uint32_t As[128 * 36];
    __shared__ __align__(16) uint32_t Bs[32 * 132];

    const int tid = threadIdx.x, lane = tid & 31, wid = tid >> 5;
    const int m0 = blockIdx.y << 7, n0 = blockIdx.x << 7;
    const int wm = (wid & 1) << 6;
    const int wn = (wid >> 1) << 5;
    const int g = lane >> 2, lt = lane & 3;

    const int am = tid >> 3, ak = (tid & 7) << 2;
    const int bk = tid >> 5, bn = (tid & 31) << 2;

    float4 acc[4][4];
#pragma unroll
    for (int t = 0; t < 4; t++)
#pragma unroll
        for (int s = 0; s < 4; s++) acc[t][s] = make_float4(0.f, 0.f, 0.f, 0.f);

    for (int k0 = 0; k0 < K; k0 += 32) {
        uint4 ta[4], tb[4];
#pragma unroll
        for (int it = 0; it < 4; it++) {
            ta[it] = cvt4(*(const float4*)(A + (long)(m0 + am + (it << 5)) * K + k0 + ak));
            tb[it] = cvt4(*(const float4*)(B + (long)(k0 + bk + (it << 3)) * N + n0 + bn));
        }
        __syncthreads();
#pragma unroll
        for (int it = 0; it < 4; it++) {
            *(uint4*)&As[(am + (it << 5)) * 36 + ak] = ta[it];
            *(uint4*)&Bs[(bk + (it << 3)) * 132 + bn] = tb[it];
        }
        __syncthreads();
#pragma unroll
        for (int kk = 0; kk < 4; kk++) {
            const int kb = kk << 3;
            uint32_t af[4][4];
#pragma unroll
            for (int t = 0; t < 4; t++) {
                int row = wm + (t << 4) + g;
                af[t][0] = As[row * 36 + kb + lt];
                af[t][1] = As[(row + 8) * 36 + kb + lt];
                af[t][2] = As[row * 36 + kb + lt + 4];
                af[t][3] = As[(row + 8) * 36 + kb + lt + 4];
            }
#pragma unroll
            for (int s = 0; s < 4; s++) {
                int col = wn + (s << 3) + g;
                uint32_t b0 = Bs[(kb + lt) * 132 + col];
                uint32_t b1 = Bs[(kb + lt + 4) * 132 + col];
#pragma unroll
                for (int t = 0; t < 4; t++) mma8(acc[t][s], af[t], b0, b1);
            }
        }
    }

#pragma unroll
    for (int t = 0; t < 4; t++) {
        int r0 = m0 + wm + (t << 4) + g;
#pragma unroll
        for (int s = 0; s < 4; s++) {
            int c = n0 + wn + (s << 3) + (lt << 1);
            float2 v0 = make_float2(acc[t][s].x, acc[t][s].y);
            float2 v1 = make_float2(acc[t][s].z, acc[t][s].w);
            if (resid) {
                float2 r4 = *(const float2*)(resid + (long)r0 * N + c);
                v0.x += r4.x; v0.y += r4.y;
                float2 r5 = *(const float2*)(resid + (long)(r0 + 8) * N + c);
                v1.x += r5.x; v1.y += r5.y;
            }
            *(float2*)(C + (long)r0 * N + c) = v0;
            *(float2*)(C + (long)(r0 + 8) * N + c) = v1;
        }
    }
}

// ---------------- fused flash with rolling BD chunks ----------------
// Grid (8 i-tiles, 128 z); block 128 threads / 4 warps; warp owns 16 full rows.
// Per j-tile: compute next 64-col G chunk ((q+u2)@r^T) into smem ring, AC mma,
// diagonal gather from 2 resident chunks, online softmax, P@V.
// Smem: Ps[64][68] @0 (17408) | St (K/r [64][132], V [64][136]) @17408 (34816)
//       Gp[2][64][68] @52224 (34816) | du[128] @87040 (512).  Total 87552.
#define FLASH_SMEM 87552

__global__ __launch_bounds__(128) void flash_pv(
    const float* __restrict__ qf, const float* __restrict__ kvf,
    const float* __restrict__ rf, const float* __restrict__ U1,
    const float* __restrict__ U2, float* __restrict__ att)
{
    extern __shared__ char dsm[];
    uint32_t* Ps = (uint32_t*)dsm;                  // [64][68]
    uint32_t* St = (uint32_t*)(dsm + 17408);        // staging (K/r stride 132, V stride 136)
    float*    Gp = (float*)(dsm + 52224);           // [2][64*68]
    float*    du = (float*)(dsm + 87040);           // [128] = u2 - u1

    const int it = blockIdx.x, z = blockIdx.y, h = z & 7;
    const int i0 = it << 6;
    const float* Q  = qf  + (long)z * 65536;
    const float* Kg = kvf + (long)z * 131072;
    const float* Vg = kvf + 16777216L + (long)z * 131072;
    const float* Rh = rf  + (long)h * 131072;
    const float* u1 = U1  + (h << 7);
    const float* u2 = U2  + (h << 7);

    const int tid = threadIdx.x, lane = tid & 31, w = tid >> 5;
    const int g = lane >> 2, lt = lane & 3;
    const int wm = w << 4;
    const int rlA = wm + g, rlB = rlA + 8;          // local rows
    const int iA = i0 + rlA, iB = i0 + rlB;         // global rows

    du[tid] = u2[tid] - u1[tid];

    // resident (q+u1) A-fragments
    uint32_t Qreg[64];
#pragma unroll
    for (int kc = 0; kc < 16; kc++) {
        int k0 = kc << 3;
        float ua = u1[k0 + lt], ub = u1[k0 + lt + 4];
        Qreg[kc * 4 + 0] = f2tf(Q[(long)iA * 128 + k0 + lt] + ua);
        Qreg[kc * 4 + 1] = f2tf(Q[(long)iB * 128 + k0 + lt] + ua);
        Qreg[kc * 4 + 2] = f2tf(Q[(long)iA * 128 + k0 + lt + 4] + ub);
        Qreg[kc * 4 + 3] = f2tf(Q[(long)iB * 128 + k0 + lt + 4] + ub);
    }
    __syncthreads();                                // du visible

    const int sr = tid >> 1, sc0 = (tid & 1) << 2;  // staging indices
    const int c00 = 448 - i0;                       // chunk 0 start column (>= 0)

    // compute G chunk m: G[:, c00+64m .. +64) -> Gp[m&1] (own-warp rows only)
    auto compute_chunk = [&](int m) {
        const int c0m = c00 + (m << 6);             // rows c0m..c0m+63 <= 1023 always
        float* Gb = Gp + ((m & 1) * 4352);
        __syncthreads();
#pragma unroll
        for (int f = 0; f < 16; f++) {
            int k = sc0 + (f << 3);
            *(uint4*)&St[sr * 132 + k] = cvt4(*(const float4*)(Rh + (long)(c0m + sr) * 128 + k));
        }
        __syncthreads();
        float4 acB[8];
#pragma unroll
        for (int s = 0; s < 8; s++) acB[s] = make_float4(0.f, 0.f, 0.f, 0.f);
#pragma unroll
        for (int kc = 0; kc < 16; kc++) {
            int kb = kc << 3;
            float dA = du[kb + lt], dB = du[kb + lt + 4];
            uint32_t a[4] = {
                f2tf(__uint_as_float(Qreg[kc * 4 + 0]) + dA),
                f2tf(__uint_as_float(Qreg[kc * 4 + 1]) + dA),
                f2tf(__uint_as_float(Qreg[kc * 4 + 2]) + dB),
                f2tf(__uint_as_float(Qreg[kc * 4 + 3]) + dB) };
#pragma unroll
            for (int s = 0; s < 8; s++) {
                int n = ((s << 3) + g) * 132 + kb + lt;
                mma8(acB[s], a, St[n], St[n + 4]);
            }
        }
#pragma unroll
        for (int s = 0; s < 8; s++) {
            int c = (s << 3) + (lt << 1);
            Gb[rlA * 68 + c]     = acB[s].x;  Gb[rlA * 68 + c + 1] = acB[s].y;
            Gb[rlB * 68 + c]     = acB[s].z;  Gb[rlB * 68 + c + 1] = acB[s].w;
        }
        __syncwarp();
    };

    compute_chunk(0);

    float4 on[16];
#pragma unroll
    for (int n = 0; n < 16; n++) on[n] = make_float4(0.f, 0.f, 0.f, 0.f);
    float mA = -1e30f, mB = -1e30f, lA = 0.f, lB = 0.f;

    const float inv = 0.08838834764831845f;         // 1/sqrt(128)
    const int capA = iA + 512, capB = iB + 512;
    const int njt = it + 9;

    for (int jt = 0; jt < njt; jt++) {
        const int j0 = jt << 6;

        if (jt + 1 < njt) compute_chunk(jt + 1);    // rolling next chunk

        // ---- stage K ----
        __syncthreads();
#pragma unroll
        for (int f = 0; f < 16; f++) {
            int k = sc0 + (f << 3);
            *(uint4*)&St[sr * 132 + k] = cvt4(*(const float4*)(Kg + (long)(j0 + sr) * 128 + k));
        }
        __syncthreads();

        // ---- AC mma ----
        float4 acS[8];
#pragma unroll
        for (int s = 0; s < 8; s++) acS[s] = make_float4(0.f, 0.f, 0.f, 0.f);
#pragma unroll
        for (int kc = 0; kc < 16; kc++) {
            const uint32_t* a = &Qreg[kc << 2];
            int kb = kc << 3;
#pragma unroll
            for (int s = 0; s < 8; s++) {
                int n = ((s << 3) + g) * 132 + kb + lt;
                mma8(acS[s], a, St[n], St[n + 4]);
            }
        }

        // ---- gather G from chunk ring, scale, mask; row max ----
        float mxA = -1e30f, mxB = -1e30f;
#pragma unroll
        for (int s = 0; s < 8; s++) {
            int jc = (s << 3) + (lt << 1);
            int j  = j0 + jc;
            int coA = 63 + jc - rlA;                // [8, 125]
            int coB = 63 + jc - rlB;                // [0, 117]
            float gx = Gp[((jt + (coA >> 6)) & 1) * 4352 + rlA * 68 + (coA & 63)];
            float gy = Gp[((jt + ((coA + 1) >> 6)) & 1) * 4352 + rlA * 68 + ((coA + 1) & 63)];
            float gz = Gp[((jt + (coB >> 6)) & 1) * 4352 + rlB * 68 + (coB & 63)];
            float gw = Gp[((jt + ((coB + 1) >> 6)) & 1) * 4352 + rlB * 68 + ((coB + 1) & 63)];
            acS[s].x = (j     <= capA) ? (acS[s].x + gx) * inv : -1e30f;
            acS[s].y = (j + 1 <= capA) ? (acS[s].y + gy) * inv : -1e30f;
            acS[s].z = (j     <= capB) ? (acS[s].z + gz) * inv : -1e30f;
            acS[s].w = (j + 1 <= capB) ? (acS[s].w + gw) * inv : -1e30f;
            mxA = fmaxf(mxA, fmaxf(acS[s].x, acS[s].y));
            mxB = fmaxf(mxB, fmaxf(acS[s].z, acS[s].w));
        }
        mxA = fmaxf(mxA, __shfl_xor_sync(0xffffffffu, mxA, 1));
        mxA = fmaxf(mxA, __shfl_xor_sync(0xffffffffu, mxA, 2));
        mxB = fmaxf(mxB, __shfl_xor_sync(0xffffffffu, mxB, 1));
        mxB = fmaxf(mxB, __shfl_xor_sync(0xffffffffu, mxB, 2));

        float mnA = fmaxf(mA, mxA), mnB = fmaxf(mB, mxB);
        float fA = __expf(mA - mnA), fB = __expf(mB - mnB);
        mA = mnA; mB = mnB;

        // ---- P = exp(S - m), partial sums, store P (per-warp region) ----
        float sA = 0.f, sB = 0.f;
#pragma unroll
        for (int s = 0; s < 8; s++) {
            int c = (s << 3) + (lt << 1);
            float p0 = __expf(acS[s].x - mnA);
            float p1 = __expf(acS[s].y - mnA);
            float p2 = __expf(acS[s].z - mnB);
            float p3 = __expf(acS[s].w - mnB);
            sA += p0 + p1; sB += p2 + p3;
            Ps[rlA * 68 + c]     = f2tf(p0);
            Ps[rlA * 68 + c + 1] = f2tf(p1);
            Ps[rlB * 68 + c]     = f2tf(p2);
            Ps[rlB * 68 + c + 1] = f2tf(p3);
        }
        sA += __shfl_xor_sync(0xffffffffu, sA, 1);
        sA += __shfl_xor_sync(0xffffffffu, sA, 2);
        sB += __shfl_xor_sync(0xffffffffu, sB, 1);
        sB += __shfl_xor_sync(0xffffffffu, sB, 2);
        lA = lA * fA + sA;
        lB = lB * fB + sB;

#pragma unroll
        for (int n = 0; n < 16; n++) {
            on[n].x *= fA; on[n].y *= fA; on[n].z *= fB; on[n].w *= fB;
        }
        __syncwarp();

        // ---- stage V ----
        __syncthreads();
#pragma unroll
        for (int f = 0; f < 16; f++) {
            int c = sc0 + (f << 3);
            *(uint4*)&St[sr * 136 + c] = cvt4(*(const float4*)(Vg + (long)(j0 + sr) * 128 + c));
        }
        __syncthreads();

        // ---- PV mma: O += P @ V ----
#pragma unroll
        for (int kc = 0; kc < 8; kc++) {
            int kb = kc << 3;
            uint32_t a[4] = { Ps[rlA * 68 + kb + lt],
                              Ps[rlB * 68 + kb + lt],
                              Ps[rlA * 68 + kb + lt + 4],
                              Ps[rlB * 68 + kb + lt + 4] };
#pragma unroll
            for (int n = 0; n < 16; n++) {
                int c = (n << 3) + g;
                mma8(on[n], a, St[(kb + lt) * 136 + c], St[(kb + lt + 4) * 136 + c]);
            }
        }
    }

    // ---- epilogue: O / l -> att (flat z-major layout) ----
    float ivA = 1.f / lA, ivB = 1.f / lB;
    float* ap = att + (long)z * 65536;
#pragma unroll
    for (int n = 0; n < 16; n++) {
        int c = (n << 3) + (lt << 1);
        *(float2*)(ap + (long)iA * 128 + c) = make_float2(on[n].x * ivA, on[n].y * ivA);
        *(float2*)(ap + (long)iB * 128 + c) = make_float2(on[n].z * ivB, on[n].w * ivB);
    }
}

// ---------------- LayerNorm over last dim (128) ----------------
__global__ __launch_bounds__(256) void ln_kernel(
    const float* __restrict__ Y, const float* __restrict__ gamma,
    const float* __restrict__ beta, float* __restrict__ out)
{
    const int row  = (blockIdx.x << 3) + (threadIdx.x >> 5);
    const int lane = threadIdx.x & 31;
    const float* y = Y + (long)row * 128;

    float4 v = *(const float4*)(y + (lane << 2));
    float s = v.x + v.y + v.z + v.w;
#pragma unroll
    for (int o = 16; o > 0; o >>= 1) s += __shfl_xor_sync(0xffffffffu, s, o);
    float mu = s * (1.0f / 128.0f);

    float dx = v.x - mu, dy = v.y - mu, dz = v.z - mu, dw = v.w - mu;
    float q = dx * dx + dy * dy + dz * dz + dw * dw;
#pragma unroll
    for (int o = 16; o > 0; o >>= 1) q += __shfl_xor_sync(0xffffffffu, q, o);
    float inv = rsqrtf(q * (1.0f / 128.0f) + 1e-5f);

    float4 g  = *(const float4*)(gamma + (lane << 2));
    float4 b4 = *(const float4*)(beta + (lane << 2));
    float4 o4;
    o4.x = dx * inv * g.x + b4.x;
    o4.y = dy * inv * g.y + b4.y;
    o4.z = dz * inv * g.z + b4.z;
    o4.w = dw * inv * g.w + b4.w;
    *(float4*)(out + (long)row * 128 + (lane << 2)) = o4;
}

// ---------------- launch ----------------
extern "C" void kernel_launch(void* const* d_in, const int* in_sizes, int n_in,
                              void* d_out, int out_size)
{
    const float* x     = (const float*)d_in[0];
    const float* mem   = (const float*)d_in[1];
    const float* R     = (const float*)d_in[2];
    // d_in[3] = att_mask (all ones; unused by reference)
    const float* u1    = (const float*)d_in[4];
    const float* u2    = (const float*)d_in[5];
    const float* Wq    = (const float*)d_in[6];
    const float* Wkv   = (const float*)d_in[7];
    const float* Wr    = (const float*)d_in[8];
    const float* Wmlp  = (const float*)d_in[9];
    const float* gamma = (const float*)d_in[10];
    const float* beta  = (const float*)d_in[11];
    float* out = (float*)d_out;

    float *hb, *qf, *kvf, *rf, *att, *yb;
    cudaGetSymbolAddress((void**)&hb,  g_h);
    cudaGetSymbolAddress((void**)&qf,  g_qf);
    cudaGetSymbolAddress((void**)&kvf, g_kvf);
    cudaGetSymbolAddress((void**)&rf,  g_rf);
    cudaGetSymbolAddress((void**)&att, g_att);
    cudaGetSymbolAddress((void**)&yb,  g_y);

    cudaFuncSetAttribute(flash_pv, cudaFuncAttributeMaxDynamicSharedMemorySize, FLASH_SMEM);

    // 1) h = concat(mem, x)
    concat_kernel<<<2048, 256>>>(x, mem, hb);
    // 2) qf = x @ Wq            (8192 x 1024, K=128)
    gemm_tf32<<<dim3(8, 64, 1), 256>>>(x, Wq, qf, 8192, 1024, 128, 0, 0, 0, nullptr);
    // 3) kvf = h @ Wkv          (16384 x 2048, K=128)
    gemm_tf32<<<dim3(16, 128, 1), 256>>>(hb, Wkv, kvf, 16384, 2048, 128, 0, 0, 0, nullptr);
    // 4) rf = R @ Wr            (1024 x 1024, K=128)
    gemm_tf32<<<dim3(8, 8, 1), 256>>>(R, Wr, rf, 1024, 1024, 128, 0, 0, 0, nullptr);
    // 5) fused: rolling BD chunks + AC + online softmax + P@V
    flash_pv<<<dim3(8, 128), 128, FLASH_SMEM>>>(qf, kvf, rf, u1, u2, att);
    // 6) y = att @ Wmlp + x     (8192 x 128, K=1024)
    gemm_tf32<<<dim3(1, 64, 1), 256>>>(att, Wmlp, yb, 8192, 128, 1024, 0, 0, 0, x);
    // 7) out = LayerNorm(y) * gamma + beta
    ln_kernel<<<1024, 256>>>(yb, gamma, beta, out);
}

// round 8
// speedup vs baseline: 1.1742x; 1.1742x over previous
#include <cuda_runtime.h>
#include <math.h>
#include <stdint.h>

// Problem constants: B=16, SEG=512, MEM=512, TOTAL=1024, MD=128, H=8, D=128

// ---------------- scratch ----------------
__device__ float g_h   [16 * 1024 * 128];          // concat(mem,x)      8 MB
__device__ float g_qf  [16 * 512 * 1024];          // x@Wq              32 MB
__device__ float g_kvf [16 * 1024 * 2048];         // h@Wkv            128 MB
__device__ float g_rf  [1024 * 1024];              // R@Wr               4 MB
__device__ float g_bd  [128ll * 512 * 1024];       // BD' (shifted G)  256 MB
__device__ float g_att [16 * 512 * 1024];          // attention out     32 MB
__device__ float g_y   [16 * 512 * 128];           // pre-LN y           4 MB

// ---------------- tf32 helpers ----------------
__device__ __forceinline__ uint32_t f2tf(float f) {
    uint32_t u; asm("cvt.rna.tf32.f32 %0, %1;" : "=r"(u) : "f"(f)); return u;
}
__device__ __forceinline__ uint4 cvt4(float4 v) {
    return make_uint4(f2tf(v.x), f2tf(v.y), f2tf(v.z), f2tf(v.w));
}
__device__ __forceinline__ float4 add4(float4 a, float4 b) {
    return make_float4(a.x + b.x, a.y + b.y, a.z + b.z, a.w + b.w);
}
__device__ __forceinline__ void mma8(float4& c, const uint32_t a[4], uint32_t b0, uint32_t b1) {
    asm volatile("mma.sync.aligned.m16n8k8.row.col.f32.tf32.tf32.f32 "
        "{%0,%1,%2,%3}, {%4,%5,%6,%7}, {%8,%9}, {%0,%1,%2,%3};"
        : "+f"(c.x), "+f"(c.y), "+f"(c.z), "+f"(c.w)
        : "r"(a[0]), "r"(a[1]), "r"(a[2]), "r"(a[3]), "r"(b0), "r"(b1));
}

// ---------------- concat(mem, x) -> g_h ----------------
__global__ __launch_bounds__(256) void concat_kernel(
    const float* __restrict__ x, const float* __restrict__ mem, float* __restrict__ hout)
{
    long idx = (long)blockIdx.x * blockDim.x + threadIdx.x;
    long e = idx * 4;
    int b   = (int)(e >> 17);
    int rem = (int)(e & 131071);
    float4 v;
    if (rem < 65536)  v = *(const float4*)(mem + (long)b * 65536 + rem);
    else              v = *(const float4*)(x   + (long)b * 65536 + rem - 65536);
    *(float4*)(hout + e) = v;
}

// ---------------- tf32 NN GEMM (block 128x128, BK=32, 256 thr) ----------------
__global__ __launch_bounds__(256) void gemm_tf32(
    const float* __restrict__ Ab, const float* __restrict__ Bb, float* __restrict__ Cb,
    int M, int N, int K, long sA, long sB, long sC, const float* __restrict__ resid)
{
    const float* A = Ab + (long)blockIdx.z * sA;
    const float* B = Bb + (long)blockIdx.z * sB;
    float*       C = Cb + (long)blockIdx.z * sC;

    __shared__ __align__(16) uint32_t As[128 * 36];
    __shared__ __align__(16) uint32_t Bs[32 * 132];

    const int tid = threadIdx.x, lane = tid & 31, wid = tid >> 5;
    const int m0 = blockIdx.y << 7, n0 = blockIdx.x << 7;
    const int wm = (wid & 1) << 6;
    const int wn = (wid >> 1) << 5;
    const int g = lane >> 2, lt = lane & 3;

    const int am = tid >> 3, ak = (tid & 7) << 2;
    const int bk = tid >> 5, bn = (tid & 31) << 2;

    float4 acc[4][4];
#pragma unroll
    for (int t = 0; t < 4; t++)
#pragma unroll
        for (int s = 0; s < 4; s++) acc[t][s] = make_float4(0.f, 0.f, 0.f, 0.f);

    for (int k0 = 0; k0 < K; k0 += 32) {
        uint4 ta[4], tb[4];
#pragma unroll
        for (int it = 0; it < 4; it++) {
            ta[it] = cvt4(*(const float4*)(A + (long)(m0 + am + (it << 5)) * K + k0 + ak));
            tb[it] = cvt4(*(const float4*)(B + (long)(k0 + bk + (it << 3)) * N + n0 + bn));
        }
        __syncthreads();
#pragma unroll
        for (int it = 0; it < 4; it++) {
            *(uint4*)&As[(am + (it << 5)) * 36 + ak] = ta[it];
            *(uint4*)&Bs[(bk + (it << 3)) * 132 + bn] = tb[it];
        }
        __syncthreads();
#pragma unroll
        for (int kk = 0; kk < 4; kk++) {
            const int kb = kk << 3;
            uint32_t af[4][4];
#pragma unroll
            for (int t = 0; t < 4; t++) {
                int row = wm + (t << 4) + g;
                af[t][0] = As[row * 36 + kb + lt];
                af[t][1] = As[(row + 8) * 36 + kb + lt];
                af[t][2] = As[row * 36 + kb + lt + 4];
                af[t][3] = As[(row + 8) * 36 + kb + lt + 4];
            }
#pragma unroll
            for (int s = 0; s < 4; s++) {
                int col = wn + (s << 3) + g;
                uint32_t b0 = Bs[(kb + lt) * 132 + col];
                uint32_t b1 = Bs[(kb + lt + 4) * 132 + col];
#pragma unroll
                for (int t = 0; t < 4; t++) mma8(acc[t][s], af[t], b0, b1);
            }
        }
    }

#pragma unroll
    for (int t = 0; t < 4; t++) {
        int r0 = m0 + wm + (t << 4) + g;
#pragma unroll
        for (int s = 0; s < 4; s++) {
            int c = n0 + wn + (s << 3) + (lt << 1);
            float2 v0 = make_float2(acc[t][s].x, acc[t][s].y);
            float2 v1 = make_float2(acc[t][s].z, acc[t][s].w);
            if (resid) {
                float2 r4 = *(const float2*)(resid + (long)r0 * N + c);
                v0.x += r4.x; v0.y += r4.y;
                float2 r5 = *(const float2*)(resid + (long)(r0 + 8) * N + c);
                v1.x += r5.x; v1.y += r5.y;
            }
            *(float2*)(C + (long)r0 * N + c) = v0;
            *(float2*)(C + (long)(r0 + 8) * N + c) = v1;
        }
    }
}

// ---------------- BD'[i][j] = [(q+u2) @ r^T][i][511+j-i], per z ----------------
// Same mainloop as an NT GEMM over G columns c; epilogue stores at j = c-511+i.
__global__ __launch_bounds__(256) void gemm_nt_bd(
    const float* __restrict__ qf, const float* __restrict__ rf,
    const float* __restrict__ U2, float* __restrict__ BDg)
{
    const int r0 = blockIdx.y << 7, c0 = blockIdx.x << 7;
    if (r0 + c0 + 254 < 511) return;     // j < 0 for entire tile
    const int z = blockIdx.z, h = z & 7;
    const float* A  = qf + (long)z * 65536;
    const float* Bm = rf + (long)h * 131072;
    float*       BD = BDg + (long)z * 524288;

    __shared__ __align__(16) uint32_t As[128 * 36];   // [m][k]
    __shared__ __align__(16) uint32_t Bs[128 * 36];   // [n][k]
    __shared__ float u2s[128];

    const int tid = threadIdx.x, lane = tid & 31, wid = tid >> 5;
    const int wm = (wid & 1) << 6;
    const int wn = (wid >> 1) << 5;
    const int g = lane >> 2, lt = lane & 3;
    const int am = tid >> 3, ak = (tid & 7) << 2;

    if (tid < 128) u2s[tid] = U2[(h << 7) + tid];
    __syncthreads();

    float4 acc[4][4];
#pragma unroll
    for (int t = 0; t < 4; t++)
#pragma unroll
        for (int s = 0; s < 4; s++) acc[t][s] = make_float4(0.f, 0.f, 0.f, 0.f);

#pragma unroll
    for (int k0 = 0; k0 < 128; k0 += 32) {
        float4 u4 = *(const float4*)&u2s[k0 + ak];
        uint4 ta[4], tb[4];
#pragma unroll
        for (int it = 0; it < 4; it++) {
            float4 av = *(const float4*)(A  + (long)(r0 + am + (it << 5)) * 128 + k0 + ak);
            ta[it] = cvt4(add4(av, u4));
            tb[it] = *(const uint4*)(Bm + (long)(c0 + am + (it << 5)) * 128 + k0 + ak);
        }
        __syncthreads();
#pragma unroll
        for (int it = 0; it < 4; it++) {
            *(uint4*)&As[(am + (it << 5)) * 36 + ak] = ta[it];
            *(uint4*)&Bs[(am + (it << 5)) * 36 + ak] = tb[it];
        }
        __syncthreads();
#pragma unroll
        for (int kk = 0; kk < 4; kk++) {
            const int kb = kk << 3;
            uint32_t af[4][4];
#pragma unroll
            for (int t = 0; t < 4; t++) {
                int row = wm + (t << 4) + g;
                af[t][0] = As[row * 36 + kb + lt];
                af[t][1] = As[(row + 8) * 36 + kb + lt];
                af[t][2] = As[row * 36 + kb + lt + 4];
                af[t][3] = As[(row + 8) * 36 + kb + lt + 4];
            }
#pragma unroll
            for (int s = 0; s < 4; s++) {
                int n = (wn + (s << 3) + g) * 36 + kb + lt;
                uint32_t b0 = Bs[n], b1 = Bs[n + 4];
#pragma unroll
                for (int t = 0; t < 4; t++) mma8(acc[t][s], af[t], b0, b1);
            }
        }
    }

    // shifted store: BD'[i][j], j = c - 511 + i  (j <= 1023 automatic)
#pragma unroll
    for (int t = 0; t < 4; t++) {
        int rA = r0 + wm + (t << 4) + g;
        int rB = rA + 8;
#pragma unroll
        for (int s = 0; s < 4; s++) {
            int c = c0 + wn + (s << 3) + (lt << 1);
            int jA = c - 511 + rA;
            int jB = c - 511 + rB;
            if (jA >= 0)     BD[(long)rA * 1024 + jA]     = acc[t][s].x;
            if (jA + 1 >= 0) BD[(long)rA * 1024 + jA + 1] = acc[t][s].y;
            if (jB >= 0)     BD[(long)rB * 1024 + jB]     = acc[t][s].z;
            if (jB + 1 >= 0) BD[(long)rB * 1024 + jB + 1] = acc[t][s].w;
        }
    }
}

// ---------------- fused flash: S=(q+u1)K^T + BD' -> online softmax -> P@V ----------------
// Grid (4 i-tiles of 128 rows, 128 z); 256 threads / 8 warps; warp owns 16 full rows.
// Smem: Ps [128][68] @0 (34816) | St (K [64][132] / V [64][136] overlay) @34816 (34816). 69632 B.
#define FLASH_SMEM 69632

__global__ __launch_bounds__(256) void flash_pv(
    const float* __restrict__ qf, const float* __restrict__ kvf,
    const float* __restrict__ BDg, const float* __restrict__ U1,
    float* __restrict__ att)
{
    extern __shared__ char dsm[];
    uint32_t* Ps = (uint32_t*)dsm;                  // [128][68]
    uint32_t* St = (uint32_t*)(dsm + 34816);        // staging (K stride 132, V stride 136)

    const int it = 3 - blockIdx.x;                  // long tiles scheduled first
    const int z = blockIdx.y, h = z & 7;
    const int i0 = it << 7;
    const float* Q  = qf  + (long)z * 65536;
    const float* Kg = kvf + (long)z * 131072;
    const float* Vg = kvf + 16777216L + (long)z * 131072;
    const float* BDz = BDg + (long)z * 524288;
    const float* u1 = U1  + (h << 7);

    const int tid = threadIdx.x, lane = tid & 31, w = tid >> 5;
    const int g = lane >> 2, lt = lane & 3;
    const int wm = w << 4;                          // 0..112
    const int rlA = wm + g, rlB = rlA + 8;          // local rows (0..127)
    const int iA = i0 + rlA, iB = i0 + rlB;         // global rows

    // resident (q+u1) A-fragments
    uint32_t Qreg[64];
#pragma unroll
    for (int kc = 0; kc < 16; kc++) {
        int k0 = kc << 3;
        float ua = u1[k0 + lt], ub = u1[k0 + lt + 4];
        Qreg[kc * 4 + 0] = f2tf(Q[(long)iA * 128 + k0 + lt] + ua);
        Qreg[kc * 4 + 1] = f2tf(Q[(long)iB * 128 + k0 + lt] + ua);
        Qreg[kc * 4 + 2] = f2tf(Q[(long)iA * 128 + k0 + lt + 4] + ub);
        Qreg[kc * 4 + 3] = f2tf(Q[(long)iB * 128 + k0 + lt + 4] + ub);
    }

    float4 on[16];
#pragma unroll
    for (int n = 0; n < 16; n++) on[n] = make_float4(0.f, 0.f, 0.f, 0.f);
    float mA = -1e30f, mB = -1e30f, lA = 0.f, lB = 0.f;

    const float inv = 0.08838834764831845f;         // 1/sqrt(128)
    const float* BA = BDz + (long)iA * 1024;
    const float* BB = BDz + (long)iB * 1024;
    const int capA = iA + 512, capB = iB + 512;
    const int njt = (it << 1) + 10;

    const int sr = tid >> 2, sc0 = (tid & 3) << 2;  // staging: 64 rows, 4 thr/row

    for (int jt = 0; jt < njt; jt++) {
        const int j0 = jt << 6;

        // ---- stage K tile raw (no cvt; truncated-tf32 operands) ----
        __syncthreads();
#pragma unroll
        for (int f = 0; f < 8; f++) {
            int k = sc0 + (f << 4);
            *(uint4*)&St[sr * 132 + k] = *(const uint4*)(Kg + (long)(j0 + sr) * 128 + k);
        }
        __syncthreads();

        // ---- AC mma ----
        float4 acS[8];
#pragma unroll
        for (int s = 0; s < 8; s++) acS[s] = make_float4(0.f, 0.f, 0.f, 0.f);
#pragma unroll
        for (int kc = 0; kc < 16; kc++) {
            const uint32_t* a = &Qreg[kc << 2];
            int kb = kc << 3;
#pragma unroll
            for (int s = 0; s < 8; s++) {
                int n = ((s << 3) + g) * 132 + kb + lt;
                mma8(acS[s], a, St[n], St[n + 4]);
            }
        }

        // ---- add BD' (coalesced float2), scale, mask; row max ----
        float mxA = -1e30f, mxB = -1e30f;
#pragma unroll
        for (int s = 0; s < 8; s++) {
            int j = j0 + (s << 3) + (lt << 1);
            float2 ga = *(const float2*)(BA + j);
            float2 gb = *(const float2*)(BB + j);
            acS[s].x = (j     <= capA) ? (acS[s].x + ga.x) * inv : -1e30f;
            acS[s].y = (j + 1 <= capA) ? (acS[s].y + ga.y) * inv : -1e30f;
            acS[s].z = (j     <= capB) ? (acS[s].z + gb.x) * inv : -1e30f;
            acS[s].w = (j + 1 <= capB) ? (acS[s].w + gb.y) * inv : -1e30f;
            mxA = fmaxf(mxA, fmaxf(acS[s].x, acS[s].y));
            mxB = fmaxf(mxB, fmaxf(acS[s].z, acS[s].w));
        }
        mxA = fmaxf(mxA, __shfl_xor_sync(0xffffffffu, mxA, 1));
        mxA = fmaxf(mxA, __shfl_xor_sync(0xffffffffu, mxA, 2));
        mxB = fmaxf(mxB, __shfl_xor_sync(0xffffffffu, mxB, 1));
        mxB = fmaxf(mxB, __shfl_xor_sync(0xffffffffu, mxB, 2));

        float mnA = fmaxf(mA, mxA), mnB = fmaxf(mB, mxB);
        float fA = __expf(mA - mnA), fB = __expf(mB - mnB);
        mA = mnA; mB = mnB;

        // ---- P = exp(S - m), partial sums, store P (per-warp rows) ----
        float sA = 0.f, sB = 0.f;
#pragma unroll
        for (int s = 0; s < 8; s++) {
            int c = (s << 3) + (lt << 1);
            float p0 = __expf(acS[s].x - mnA);
            float p1 = __expf(acS[s].y - mnA);
            float p2 = __expf(acS[s].z - mnB);
            float p3 = __expf(acS[s].w - mnB);
            sA += p0 + p1; sB += p2 + p3;
            Ps[rlA * 68 + c]     = f2tf(p0);
            Ps[rlA * 68 + c + 1] = f2tf(p1);
            Ps[rlB * 68 + c]     = f2tf(p2);
            Ps[rlB * 68 + c + 1] = f2tf(p3);
        }
        sA += __shfl_xor_sync(0xffffffffu, sA, 1);
        sA += __shfl_xor_sync(0xffffffffu, sA, 2);
        sB += __shfl_xor_sync(0xffffffffu, sB, 1);
        sB += __shfl_xor_sync(0xffffffffu, sB, 2);
        lA = lA * fA + sA;
        lB = lB * fB + sB;

#pragma unroll
        for (int n = 0; n < 16; n++) {
            on[n].x *= fA; on[n].y *= fA; on[n].z *= fB; on[n].w *= fB;
        }
        __syncwarp();

        // ---- stage V tile raw (overlay) ----
        __syncthreads();
#pragma unroll
        for (int f = 0; f < 8; f++) {
            int c = sc0 + (f << 4);
            *(uint4*)&St[sr * 136 + c] = *(const uint4*)(Vg + (long)(j0 + sr) * 128 + c);
        }
        __syncthreads();

        // ---- PV mma: O += P @ V ----
#pragma unroll
        for (int kc = 0; kc < 8; kc++) {
            int kb = kc << 3;
            uint32_t a[4] = { Ps[rlA * 68 + kb + lt],
                              Ps[rlB * 68 + kb + lt],
                              Ps[rlA * 68 + kb + lt + 4],
                              Ps[rlB * 68 + kb + lt + 4] };
#pragma unroll
            for (int n = 0; n < 16; n++) {
                int c = (n << 3) + g;
                mma8(on[n], a, St[(kb + lt) * 136 + c], St[(kb + lt + 4) * 136 + c]);
            }
        }
    }

    // ---- epilogue: O / l -> att (flat z-major layout) ----
    float ivA = 1.f / lA, ivB = 1.f / lB;
    float* ap = att + (long)z * 65536;
#pragma unroll
    for (int n = 0; n < 16; n++) {
        int c = (n << 3) + (lt << 1);
        *(float2*)(ap + (long)iA * 128 + c) = make_float2(on[n].x * ivA, on[n].y * ivA);
        *(float2*)(ap + (long)iB * 128 + c) = make_float2(on[n].z * ivB, on[n].w * ivB);
    }
}

// ---------------- LayerNorm over last dim (128) ----------------
__global__ __launch_bounds__(256) void ln_kernel(
    const float* __restrict__ Y, const float* __restrict__ gamma,
    const float* __restrict__ beta, float* __restrict__ out)
{
    const int row  = (blockIdx.x << 3) + (threadIdx.x >> 5);
    const int lane = threadIdx.x & 31;
    const float* y = Y + (long)row * 128;

    float4 v = *(const float4*)(y + (lane << 2));
    float s = v.x + v.y + v.z + v.w;
#pragma unroll
    for (int o = 16; o > 0; o >>= 1) s += __shfl_xor_sync(0xffffffffu, s, o);
    float mu = s * (1.0f / 128.0f);

    float dx = v.x - mu, dy = v.y - mu, dz = v.z - mu, dw = v.w - mu;
    float q = dx * dx + dy * dy + dz * dz + dw * dw;
#pragma unroll
    for (int o = 16; o > 0; o >>= 1) q += __shfl_xor_sync(0xffffffffu, q, o);
    float inv = rsqrtf(q * (1.0f / 128.0f) + 1e-5f);

    float4 g  = *(const float4*)(gamma + (lane << 2));
    float4 b4 = *(const float4*)(beta + (lane << 2));
    float4 o4;
    o4.x = dx * inv * g.x + b4.x;
    o4.y = dy * inv * g.y + b4.y;
    o4.z = dz * inv * g.z + b4.z;
    o4.w = dw * inv * g.w + b4.w;
    *(float4*)(out + (long)row * 128 + (lane << 2)) = o4;
}

// ---------------- launch ----------------
extern "C" void kernel_launch(void* const* d_in, const int* in_sizes, int n_in,
                              void* d_out, int out_size)
{
    const float* x     = (const float*)d_in[0];
    const float* mem   = (const float*)d_in[1];
    const float* R     = (const float*)d_in[2];
    // d_in[3] = att_mask (all ones; unused by reference)
    const float* u1    = (const float*)d_in[4];
    const float* u2    = (const float*)d_in[5];
    const float* Wq    = (const float*)d_in[6];
    const float* Wkv   = (const float*)d_in[7];
    const float* Wr    = (const float*)d_in[8];
    const float* Wmlp  = (const float*)d_in[9];
    const float* gamma = (const float*)d_in[10];
    const float* beta  = (const float*)d_in[11];
    float* out = (float*)d_out;

    float *hb, *qf, *kvf, *rf, *bd, *att, *yb;
    cudaGetSymbolAddress((void**)&hb,  g_h);
    cudaGetSymbolAddress((void**)&qf,  g_qf);
    cudaGetSymbolAddress((void**)&kvf, g_kvf);
    cudaGetSymbolAddress((void**)&rf,  g_rf);
    cudaGetSymbolAddress((void**)&bd,  g_bd);
    cudaGetSymbolAddress((void**)&att, g_att);
    cudaGetSymbolAddress((void**)&yb,  g_y);

    cudaFuncSetAttribute(flash_pv, cudaFuncAttributeMaxDynamicSharedMemorySize, FLASH_SMEM);

    // 1) h = concat(mem, x)
    concat_kernel<<<2048, 256>>>(x, mem, hb);
    // 2) qf = x @ Wq            (8192 x 1024, K=128)
    gemm_tf32<<<dim3(8, 64, 1), 256>>>(x, Wq, qf, 8192, 1024, 128, 0, 0, 0, nullptr);
    // 3) kvf = h @ Wkv          (16384 x 2048, K=128)
    gemm_tf32<<<dim3(16, 128, 1), 256>>>(hb, Wkv, kvf, 16384, 2048, 128, 0, 0, 0, nullptr);
    // 4) rf = R @ Wr            (1024 x 1024, K=128)
    gemm_tf32<<<dim3(8, 8, 1), 256>>>(R, Wr, rf, 1024, 1024, 128, 0, 0, 0, nullptr);
    // 5) BD'[i][j] = [(q+u2)@r^T][i][511+j-i]   (banded tiles only)
    gemm_nt_bd<<<dim3(8, 4, 128), 256>>>(qf, rf, u2, bd);
    // 6) fused: S = ((q+u1)K^T + BD')/sqrt(d) -> online softmax -> att = P@V
    flash_pv<<<dim3(4, 128), 256, FLASH_SMEM>>>(qf, kvf, bd, u1, att);
    // 7) y = att @ Wmlp + x     (8192 x 128, K=1024)
    gemm_tf32<<<dim3(1, 64, 1), 256>>>(att, Wmlp, yb, 8192, 128, 1024, 0, 0, 0, x);
    // 8) out = LayerNorm(y) * gamma + beta
    ln_kernel<<<1024, 256>>>(yb, gamma, beta, out);
}